// round 14
// baseline (speedup 1.0000x reference)
#include <cuda_runtime.h>
#include <cuda_fp16.h>
#include <cstdint>
#include <math.h>

#define IN_DIM 1000
#define KP1 1024
#define HD 256
#define ZD 32
#define NP 64
#define NC 8
#define NB 64
#define MBLK64 3128
#define NPAD (MBLK64 * 64)      /* 200192 */

// ---------------- device scratch ----------------
__device__ __align__(16) float  g_z  [(size_t)NPAD * ZD];
__device__ __align__(16) __half g_w1p[256 * KP1];
__device__ __align__(16) __half g_w2p[256 * HD];
__device__ __align__(16) __half g_wzp[32 * HD];
__device__ float g_bagsum[NB * NC];
__device__ float g_bagcnt[NB];

__device__ __forceinline__ float lrelu(float v) { return v > 0.0f ? v : 0.01f * v; }

__device__ __forceinline__ uint32_t s2u(const void* p) {
    uint32_t a;
    asm("{ .reg .u64 t; cvta.to.shared.u64 t, %1; cvt.u32.u64 %0, t; }" : "=r"(a) : "l"(p));
    return a;
}
__device__ __forceinline__ void cpa16(uint32_t dst, const void* src) {
    asm volatile("cp.async.cg.shared.global [%0], [%1], 16;" :: "r"(dst), "l"(src) : "memory");
}
__device__ __forceinline__ void ldx4(uint32_t& r0, uint32_t& r1, uint32_t& r2, uint32_t& r3,
                                     uint32_t addr) {
    asm volatile("ldmatrix.sync.aligned.m8n8.x4.shared.b16 {%0,%1,%2,%3}, [%4];"
                 : "=r"(r0), "=r"(r1), "=r"(r2), "=r"(r3) : "r"(addr));
}
__device__ __forceinline__ void mma16816(float (&c)[4], const uint32_t (&a)[4],
                                         uint32_t b0, uint32_t b1) {
    asm volatile(
        "mma.sync.aligned.m16n8k16.row.col.f32.f16.f16.f32 "
        "{%0,%1,%2,%3}, {%4,%5,%6,%7}, {%8,%9}, {%0,%1,%2,%3};"
        : "+f"(c[0]), "+f"(c[1]), "+f"(c[2]), "+f"(c[3])
        : "r"(a[0]), "r"(a[1]), "r"(a[2]), "r"(a[3]), "r"(b0), "r"(b1));
}

// ---------------- prep: zero accum + pack all weights to fp16 ----------------
__global__ void pack_all_kernel(const float* __restrict__ Wi, const float* __restrict__ Wh,
                                const float* __restrict__ Wz) {
    int idx = blockIdx.x * 256 + threadIdx.x;
    if (blockIdx.x == 0) {
        for (int t = threadIdx.x; t < NB * NC; t += 256) g_bagsum[t] = 0.0f;
        if (threadIdx.x < NB) g_bagcnt[threadIdx.x] = 0.0f;
    }
    if (idx < 256 * KP1) {
        int r = idx >> 10, k = idx & 1023;
        g_w1p[idx] = __float2half_rn(k < IN_DIM ? Wi[r * IN_DIM + k] : 0.0f);
    } else if (idx < 256 * KP1 + 256 * HD) {
        int j = idx - 256 * KP1;
        g_w2p[j] = __float2half_rn(Wh[j]);
    } else if (idx < 256 * KP1 + 256 * HD + ZD * HD) {
        int j = idx - 256 * KP1 - 256 * HD;
        g_wzp[j] = __float2half_rn(Wz[j]);
    }
}

// =================== fused encoder: x -> h1(smem) -> h2(smem) -> z ===================
// 256 threads, 64-row tile, occupancy 2.
#define ASTG 5120                           /* 64 rows * 80B */
#define BSTG 20480                          /* 256 rows * 80B */
#define OFF_A 0                             /* 2 stages -> 10240 */
#define OFF_B 10240                         /* 3 stages -> 71680 */
#define OFF_WZ (OFF_B + 2 * BSTG)           /* 51200 : Wz (32 x 528B) in B stage 2, late */
#define OFF_H 71680                         /* 64 x 528B = 33792 */
#define OFF_B1 105472                       /* 1024 */
#define OFF_B2 106496                       /* 1024 */
#define OFF_BZ 107520                       /* 128 */
#define SMEMT 107648

__global__ __launch_bounds__(256, 2)
void encoder_kernel(const float* __restrict__ X,
                    const __half* __restrict__ w1p, const __half* __restrict__ w2p,
                    const __half* __restrict__ wzp,
                    const float* __restrict__ b_i, const float* __restrict__ b_h,
                    const float* __restrict__ b_z,
                    float* __restrict__ zout, int N)
{
    extern __shared__ char smem[];
    const uint32_t su = s2u(smem);
    const int tid = threadIdx.x, lane = tid & 31, wid = tid >> 5;
    const int warp_m = wid & 1, warp_n = wid >> 1;      // 2 x 4 warps, 32x64 warp tile
    const size_t rowbase = (size_t)blockIdx.x * 64;

    float* s_b1 = (float*)(smem + OFF_B1);
    float* s_b2 = (float*)(smem + OFF_B2);
    float* s_bz = (float*)(smem + OFF_BZ);
    s_b1[tid] = b_i[tid];
    s_b2[tid] = b_h[tid];
    if (tid < ZD) s_bz[tid] = b_z[tid];

    const int a_r = lane & 15, a_k = (lane >> 4) * 8;
    const int b_n = (lane & 7) + ((lane >> 4) << 3);
    const int b_k = ((lane >> 3) & 1) * 8;

    float acc[2][8][4];
#pragma unroll
    for (int mt = 0; mt < 2; mt++)
#pragma unroll
        for (int nt = 0; nt < 8; nt++)
#pragma unroll
            for (int i = 0; i < 4; i++) acc[mt][nt][i] = 0.0f;

    // ================= PHASE 1: h1 = lrelu(x @ W1^T + b_i) -> smem tile =================
    {
        const int arow = tid >> 2;              // 0..63
        const int akq  = (tid & 3) * 8;
        const bool rowok = (rowbase + arow) < (size_t)N;
        const float* xrow = X + (rowbase + arow) * IN_DIM;

        float4 ar0, ar1;
        auto ldgA = [&](int c) {
            int k = c * 32 + akq;
            ar0 = (rowok && k     < IN_DIM) ? *reinterpret_cast<const float4*>(xrow + k)
                                            : make_float4(0.f, 0.f, 0.f, 0.f);
            ar1 = (rowok && k + 4 < IN_DIM) ? *reinterpret_cast<const float4*>(xrow + k + 4)
                                            : make_float4(0.f, 0.f, 0.f, 0.f);
        };
        auto stsA = [&](int st) {
            __half2 h[4];
            h[0] = __floats2half2_rn(ar0.x, ar0.y); h[1] = __floats2half2_rn(ar0.z, ar0.w);
            h[2] = __floats2half2_rn(ar1.x, ar1.y); h[3] = __floats2half2_rn(ar1.z, ar1.w);
            *reinterpret_cast<uint4*>(smem + OFF_A + st * ASTG + arow * 80 + (tid & 3) * 16)
                = *reinterpret_cast<uint4*>(h);
        };
        auto cpB1 = [&](int c, int st) {
            const uint32_t bb = su + OFF_B + st * BSTG;
#pragma unroll
            for (int i = 0; i < 4; i++) {
                int s = tid + i * 256;
                int row = s >> 2, seg = s & 3;
                cpa16(bb + row * 80 + seg * 16, w1p + (size_t)row * KP1 + c * 32 + seg * 8);
            }
            asm volatile("cp.async.commit_group;" ::: "memory");
        };

        ldgA(0); stsA(0);
        ldgA(1);
        cpB1(0, 0); cpB1(1, 1);

        constexpr int NCH = KP1 / 32;           // 32 ; 3-stage, depth-2 prefetch
        for (int c = 0; c < NCH; c++) {
            if (c < NCH - 1) asm volatile("cp.async.wait_group 1;" ::: "memory");
            else             asm volatile("cp.async.wait_group 0;" ::: "memory");
            __syncthreads();
            if (c + 2 < NCH) cpB1(c + 2, (c + 2) % 3);
            if (c + 1 < NCH) stsA((c + 1) & 1);
            if (c + 2 < NCH) ldgA(c + 2);

            const uint32_t ab = su + OFF_A + (c & 1) * ASTG;
            const uint32_t bb = su + OFF_B + (c % 3) * BSTG;
#pragma unroll
            for (int s = 0; s < 2; s++) {
                uint32_t a[2][4];
#pragma unroll
                for (int mt = 0; mt < 2; mt++)
                    ldx4(a[mt][0], a[mt][1], a[mt][2], a[mt][3],
                         ab + (warp_m * 32 + mt * 16 + a_r) * 80 + (s * 16 + a_k) * 2);
                uint32_t b[4][4];
#pragma unroll
                for (int p = 0; p < 4; p++)
                    ldx4(b[p][0], b[p][1], b[p][2], b[p][3],
                         bb + (warp_n * 64 + p * 16 + b_n) * 80 + (s * 16 + b_k) * 2);
#pragma unroll
                for (int mt = 0; mt < 2; mt++)
#pragma unroll
                    for (int nt = 0; nt < 8; nt++)
                        mma16816(acc[mt][nt], a[mt], b[nt >> 1][(nt & 1) * 2],
                                 b[nt >> 1][(nt & 1) * 2 + 1]);
            }
        }

        // epilogue: h1 -> smem tile (fp16, 528B stride). H region is untouched so far.
#pragma unroll
        for (int mt = 0; mt < 2; mt++) {
#pragma unroll
            for (int nt = 0; nt < 8; nt++) {
                int col = warp_n * 64 + nt * 8 + (lane & 3) * 2;
                int r0 = warp_m * 32 + mt * 16 + (lane >> 2);
                float v0 = lrelu(acc[mt][nt][0] + s_b1[col]);
                float v1 = lrelu(acc[mt][nt][1] + s_b1[col + 1]);
                float v2 = lrelu(acc[mt][nt][2] + s_b1[col]);
                float v3 = lrelu(acc[mt][nt][3] + s_b1[col + 1]);
                *reinterpret_cast<__half2*>(smem + OFF_H + r0 * 528 + col * 2) =
                    __floats2half2_rn(v0, v1);
                *reinterpret_cast<__half2*>(smem + OFF_H + (r0 + 8) * 528 + col * 2) =
                    __floats2half2_rn(v2, v3);
            }
        }
    }
    __syncthreads();   // h1 visible; all phase-1 stage reads finished

    // ================= PHASE 2: h2 = lrelu(h1 @ W2^T + b_h), A from smem tile =================
    {
        auto cpB2 = [&](int c, int st) {
            const uint32_t bb = su + OFF_B + st * BSTG;
#pragma unroll
            for (int i = 0; i < 4; i++) {
                int s = tid + i * 256;
                int row = s >> 2, seg = s & 3;
                cpa16(bb + row * 80 + seg * 16, w2p + (size_t)row * HD + c * 32 + seg * 8);
            }
            asm volatile("cp.async.commit_group;" ::: "memory");
        };
        auto cpWz = [&]() {   // Wz (32 x 256 fp16) -> B stage 2 region, 528B stride
#pragma unroll
            for (int i = 0; i < 4; i++) {
                int s = tid + i * 256;
                int row = s >> 5, seg = s & 31;
                cpa16(su + OFF_WZ + row * 528 + seg * 16, wzp + (size_t)row * HD + seg * 8);
            }
            asm volatile("cp.async.commit_group;" ::: "memory");
        };

#pragma unroll
        for (int mt = 0; mt < 2; mt++)
#pragma unroll
            for (int nt = 0; nt < 8; nt++)
#pragma unroll
                for (int i = 0; i < 4; i++) acc[mt][nt][i] = 0.0f;

        cpB2(0, 0); cpB2(1, 1);

        const uint32_t hb = su + OFF_H;
        constexpr int NCH = HD / 32;            // 8
        for (int c = 0; c < NCH; c++) {
            if (c < NCH - 1) asm volatile("cp.async.wait_group 1;" ::: "memory");
            else             asm volatile("cp.async.wait_group 0;" ::: "memory");
            __syncthreads();
            if (c + 2 < NCH) cpB2(c + 2, (c + 2) % 3);
            if (c == 6) cpWz();                 // stage-2 region dead after chunk 5

            const uint32_t bb = su + OFF_B + (c % 3) * BSTG;
#pragma unroll
            for (int s = 0; s < 2; s++) {
                uint32_t a[2][4];
#pragma unroll
                for (int mt = 0; mt < 2; mt++)
                    ldx4(a[mt][0], a[mt][1], a[mt][2], a[mt][3],
                         hb + (warp_m * 32 + mt * 16 + a_r) * 528 + (c * 32 + s * 16 + a_k) * 2);
                uint32_t b[4][4];
#pragma unroll
                for (int p = 0; p < 4; p++)
                    ldx4(b[p][0], b[p][1], b[p][2], b[p][3],
                         bb + (warp_n * 64 + p * 16 + b_n) * 80 + (s * 16 + b_k) * 2);
#pragma unroll
                for (int mt = 0; mt < 2; mt++)
#pragma unroll
                    for (int nt = 0; nt < 8; nt++)
                        mma16816(acc[mt][nt], a[mt], b[nt >> 1][(nt & 1) * 2],
                                 b[nt >> 1][(nt & 1) * 2 + 1]);
            }
        }
        __syncthreads();    // all h1 reads done before overwrite

        // epilogue: h2 overwrites the H tile
#pragma unroll
        for (int mt = 0; mt < 2; mt++) {
#pragma unroll
            for (int nt = 0; nt < 8; nt++) {
                int col = warp_n * 64 + nt * 8 + (lane & 3) * 2;
                int r0 = warp_m * 32 + mt * 16 + (lane >> 2);
                float v0 = lrelu(acc[mt][nt][0] + s_b2[col]);
                float v1 = lrelu(acc[mt][nt][1] + s_b2[col + 1]);
                float v2 = lrelu(acc[mt][nt][2] + s_b2[col]);
                float v3 = lrelu(acc[mt][nt][3] + s_b2[col + 1]);
                *reinterpret_cast<__half2*>(smem + OFF_H + r0 * 528 + col * 2) =
                    __floats2half2_rn(v0, v1);
                *reinterpret_cast<__half2*>(smem + OFF_H + (r0 + 8) * 528 + col * 2) =
                    __floats2half2_rn(v2, v3);
            }
        }
    }
    __syncthreads();

    // ================= PHASE 3: z = lrelu(h2 @ Wz^T + bz), warps 0..3 =================
    if (wid < 4) {
        float zacc[4][4];
#pragma unroll
        for (int nt = 0; nt < 4; nt++)
#pragma unroll
            for (int i = 0; i < 4; i++) zacc[nt][i] = 0.0f;

        const uint32_t hb = su + OFF_H;
        const uint32_t wzb = su + OFF_WZ;
        const int arow = wid * 16 + a_r;
#pragma unroll 4
        for (int s = 0; s < 16; s++) {
            uint32_t a[4];
            ldx4(a[0], a[1], a[2], a[3], hb + arow * 528 + (s * 16 + a_k) * 2);
            uint32_t b[2][4];
#pragma unroll
            for (int p = 0; p < 2; p++)
                ldx4(b[p][0], b[p][1], b[p][2], b[p][3],
                     wzb + (p * 16 + b_n) * 528 + (s * 16 + b_k) * 2);
#pragma unroll
            for (int nt = 0; nt < 4; nt++)
                mma16816(zacc[nt], a, b[nt >> 1][(nt & 1) * 2], b[nt >> 1][(nt & 1) * 2 + 1]);
        }
#pragma unroll
        for (int nt = 0; nt < 4; nt++) {
            int col = nt * 8 + (lane & 3) * 2;
            int r0 = wid * 16 + (lane >> 2);
            float2 v0, v1;
            v0.x = lrelu(zacc[nt][0] + s_bz[col]);
            v0.y = lrelu(zacc[nt][1] + s_bz[col + 1]);
            v1.x = lrelu(zacc[nt][2] + s_bz[col]);
            v1.y = lrelu(zacc[nt][3] + s_bz[col + 1]);
            *reinterpret_cast<float2*>(zout + (rowbase + r0) * ZD + col) = v0;
            *reinterpret_cast<float2*>(zout + (rowbase + r0 + 8) * ZD + col) = v1;
        }
    }
}

// ---------------- head: 2 cells/thread, warp-uniform segmented reduction ----------------
__global__ __launch_bounds__(256)
void head_kernel(const float* __restrict__ zin, const int* __restrict__ seg,
                 const float* __restrict__ protos, const float* __restrict__ Wclf, int N)
{
    __shared__ float sProto[NP * ZD];
    __shared__ float sPsq[NP];
    __shared__ float sWclf[NC * NP];
    __shared__ float sBag[NB * NC];
    __shared__ float sCnt[NB];

    const int tid = threadIdx.x;
    for (int i = tid; i < NP * ZD; i += 256) sProto[i] = protos[i];
    for (int i = tid; i < NC * NP; i += 256) sWclf[i] = Wclf[i];
    for (int i = tid; i < NB * NC; i += 256) sBag[i] = 0.0f;
    if (tid < NB) sCnt[tid] = 0.0f;
    __syncthreads();
    if (tid < NP) {
        float s = 0.0f;
#pragma unroll
        for (int j = 0; j < ZD; j++) { float p = sProto[tid * ZD + j]; s = fmaf(p, p, s); }
        sPsq[tid] = s;
    }
    __syncthreads();

    const int lane = tid & 31;
    const int cell0 = blockIdx.x * 512 + tid;
    const int cell1 = cell0 + 256;
    const bool v0ok = cell0 < N, v1ok = cell1 < N;

    float z0[ZD], z1[ZD];
    float zsq0 = 0.0f, zsq1 = 0.0f;
    if (v0ok) {
        const float4* zr = reinterpret_cast<const float4*>(zin + (size_t)cell0 * ZD);
#pragma unroll
        for (int j4 = 0; j4 < ZD / 4; j4++) {
            float4 v = zr[j4];
            z0[j4 * 4 + 0] = v.x; z0[j4 * 4 + 1] = v.y;
            z0[j4 * 4 + 2] = v.z; z0[j4 * 4 + 3] = v.w;
        }
#pragma unroll
        for (int j = 0; j < ZD; j++) zsq0 = fmaf(z0[j], z0[j], zsq0);
    } else {
#pragma unroll
        for (int j = 0; j < ZD; j++) z0[j] = 0.0f;
    }
    if (v1ok) {
        const float4* zr = reinterpret_cast<const float4*>(zin + (size_t)cell1 * ZD);
#pragma unroll
        for (int j4 = 0; j4 < ZD / 4; j4++) {
            float4 v = zr[j4];
            z1[j4 * 4 + 0] = v.x; z1[j4 * 4 + 1] = v.y;
            z1[j4 * 4 + 2] = v.z; z1[j4 * 4 + 3] = v.w;
        }
#pragma unroll
        for (int j = 0; j < ZD; j++) zsq1 = fmaf(z1[j], z1[j], zsq1);
    } else {
#pragma unroll
        for (int j = 0; j < ZD; j++) z1[j] = 0.0f;
    }

    float cl0[NC], cl1[NC];
#pragma unroll
    for (int c = 0; c < NC; c++) { cl0[c] = 0.0f; cl1[c] = 0.0f; }

#pragma unroll 2
    for (int p = 0; p < NP; p++) {
        const float4* pp = reinterpret_cast<const float4*>(&sProto[p * ZD]);
        float d0 = 0.0f, d1 = 0.0f;
#pragma unroll
        for (int j4 = 0; j4 < ZD / 4; j4++) {
            float4 pv = pp[j4];
            d0 = fmaf(z0[j4 * 4 + 0], pv.x, d0); d1 = fmaf(z1[j4 * 4 + 0], pv.x, d1);
            d0 = fmaf(z0[j4 * 4 + 1], pv.y, d0); d1 = fmaf(z1[j4 * 4 + 1], pv.y, d1);
            d0 = fmaf(z0[j4 * 4 + 2], pv.z, d0); d1 = fmaf(z1[j4 * 4 + 2], pv.z, d1);
            d0 = fmaf(z0[j4 * 4 + 3], pv.w, d0); d1 = fmaf(z1[j4 * 4 + 3], pv.w, d1);
        }
        float dd0 = zsq0 - 2.0f * d0 + sPsq[p] + 0.5f;
        float dd1 = zsq1 - 2.0f * d1 + sPsq[p] + 0.5f;
        float inv0 = __fdividef(1.0f, dd0);
        float inv1 = __fdividef(1.0f, dd1);
#pragma unroll
        for (int c = 0; c < NC; c++) {
            float w = sWclf[c * NP + p];
            cl0[c] = fmaf(inv0, w, cl0[c]);
            cl1[c] = fmaf(inv1, w, cl1[c]);
        }
    }

    int b0 = v0ok ? seg[cell0] : -1;
    int b1 = v1ok ? seg[cell1] : -1;

    {
        const int bb = __shfl_sync(0xFFFFFFFFu, b0, 0);
        const bool uni = __all_sync(0xFFFFFFFFu, b0 == bb && b0 >= 0);
        if (uni) {
#pragma unroll
            for (int off = 16; off > 0; off >>= 1)
#pragma unroll
                for (int c = 0; c < NC; c++)
                    cl0[c] += __shfl_xor_sync(0xFFFFFFFFu, cl0[c], off);
            if (lane < NC) atomicAdd(&sBag[bb * NC + lane], cl0[lane]);
            else if (lane == NC) atomicAdd(&sCnt[bb], 32.0f);
        } else if (v0ok) {
#pragma unroll
            for (int c = 0; c < NC; c++) atomicAdd(&sBag[b0 * NC + c], cl0[c]);
            atomicAdd(&sCnt[b0], 1.0f);
        }
    }
    {
        const int bb = __shfl_sync(0xFFFFFFFFu, b1, 0);
        const bool uni = __all_sync(0xFFFFFFFFu, b1 == bb && b1 >= 0);
        if (uni) {
#pragma unroll
            for (int off = 16; off > 0; off >>= 1)
#pragma unroll
                for (int c = 0; c < NC; c++)
                    cl1[c] += __shfl_xor_sync(0xFFFFFFFFu, cl1[c], off);
            if (lane < NC) atomicAdd(&sBag[bb * NC + lane], cl1[lane]);
            else if (lane == NC) atomicAdd(&sCnt[bb], 32.0f);
        } else if (v1ok) {
#pragma unroll
            for (int c = 0; c < NC; c++) atomicAdd(&sBag[b1 * NC + c], cl1[c]);
            atomicAdd(&sCnt[b1], 1.0f);
        }
    }
    __syncthreads();

    for (int i = tid; i < NB * NC; i += 256)
        if (sBag[i] != 0.0f) atomicAdd(&g_bagsum[i], sBag[i]);
    if (tid < NB && sCnt[tid] != 0.0f) atomicAdd(&g_bagcnt[tid], sCnt[tid]);
}

// ---------------- finalize ----------------
__global__ void finalize_kernel(const int* __restrict__ y, float* __restrict__ out,
                                int out_size)
{
    __shared__ float sLoss[NB];
    const int b = threadIdx.x;
    float l[NC];
    float cnt = fmaxf(g_bagcnt[b], 1.0f);
    float inv = 1.0f / cnt;
    float m = -1e30f;
#pragma unroll
    for (int c = 0; c < NC; c++) { l[c] = g_bagsum[b * NC + c] * inv; m = fmaxf(m, l[c]); }
    float se = 0.0f;
#pragma unroll
    for (int c = 0; c < NC; c++) se += expf(l[c] - m);
    float lse = logf(se);
    int yc = y[b];
    sLoss[b] = -(l[yc] - m - lse);

    float* lo;
    bool write_loss;
    if (out_size == NB * NC) { lo = out; write_loss = false; }
    else                     { lo = out + 1; write_loss = true; }
    if (out_size >= NB * NC) {
#pragma unroll
        for (int c = 0; c < NC; c++) lo[b * NC + c] = l[c];
    }
    __syncthreads();
    if (b == 0 && write_loss) {
        float s = 0.0f;
        for (int i = 0; i < NB; i++) s += sLoss[i];
        out[0] = s / (float)NB;
    }
}

// ---------------- launch ----------------
extern "C" void kernel_launch(void* const* d_in, const int* in_sizes, int n_in,
                              void* d_out, int out_size)
{
    const float* x      = (const float*)d_in[0];
    const int*   y      = (const int*)  d_in[1];
    const int*   seg    = (const int*)  d_in[2];
    const float* W_i    = (const float*)d_in[3];
    const float* b_i    = (const float*)d_in[4];
    const float* W_h    = (const float*)d_in[5];
    const float* b_h    = (const float*)d_in[6];
    const float* W_z    = (const float*)d_in[7];
    const float* b_z    = (const float*)d_in[8];
    const float* protos = (const float*)d_in[9];
    const float* W_clf  = (const float*)d_in[10];

    const int N = in_sizes[0] / IN_DIM;

    __half *w1p, *w2p, *wzp;
    float* z;
    cudaGetSymbolAddress((void**)&z,   g_z);
    cudaGetSymbolAddress((void**)&w1p, g_w1p);
    cudaGetSymbolAddress((void**)&w2p, g_w2p);
    cudaGetSymbolAddress((void**)&wzp, g_wzp);

    cudaFuncSetAttribute(encoder_kernel, cudaFuncAttributeMaxDynamicSharedMemorySize, SMEMT);

    const int pack_total = 256 * KP1 + 256 * HD + ZD * HD;
    pack_all_kernel<<<(pack_total + 255) / 256, 256>>>(W_i, W_h, W_z);

    encoder_kernel<<<MBLK64, 256, SMEMT>>>(x, w1p, w2p, wzp, b_i, b_h, b_z, z, N);

    head_kernel<<<NPAD / 512, 256>>>(z, seg, protos, W_clf, N);
    finalize_kernel<<<1, NB>>>(y, (float*)d_out, out_size);
}

// round 15
// speedup vs baseline: 1.4692x; 1.4692x over previous
#include <cuda_runtime.h>
#include <cuda_fp16.h>
#include <cstdint>
#include <math.h>

#define IN_DIM 1000
#define KP1 1024
#define HD 256
#define ZD 32
#define NP 64
#define NC 8
#define NB 64
#define MBLK 1564
#define NPAD (MBLK * 128)
#define MBLK64 (NPAD / 64)

// ---------------- device scratch ----------------
__device__ __align__(16) __half g_h1 [(size_t)NPAD * HD];
__device__ __align__(16) float  g_z  [(size_t)NPAD * ZD];
__device__ __align__(16) __half g_w1p[256 * KP1];
__device__ __align__(16) __half g_w2p[256 * HD];
__device__ __align__(16) __half g_wzp[32 * HD];
__device__ float g_bagsum[NB * NC];
__device__ float g_bagcnt[NB];

__device__ __forceinline__ float lrelu(float v) { return v > 0.0f ? v : 0.01f * v; }

__device__ __forceinline__ uint32_t s2u(const void* p) {
    uint32_t a;
    asm("{ .reg .u64 t; cvta.to.shared.u64 t, %1; cvt.u32.u64 %0, t; }" : "=r"(a) : "l"(p));
    return a;
}
__device__ __forceinline__ void cpa16(uint32_t dst, const void* src) {
    asm volatile("cp.async.cg.shared.global [%0], [%1], 16;" :: "r"(dst), "l"(src) : "memory");
}
__device__ __forceinline__ void ldx4(uint32_t& r0, uint32_t& r1, uint32_t& r2, uint32_t& r3,
                                     uint32_t addr) {
    asm volatile("ldmatrix.sync.aligned.m8n8.x4.shared.b16 {%0,%1,%2,%3}, [%4];"
                 : "=r"(r0), "=r"(r1), "=r"(r2), "=r"(r3) : "r"(addr));
}
__device__ __forceinline__ void mma16816(float (&c)[4], const uint32_t (&a)[4],
                                         uint32_t b0, uint32_t b1) {
    asm volatile(
        "mma.sync.aligned.m16n8k16.row.col.f32.f16.f16.f32 "
        "{%0,%1,%2,%3}, {%4,%5,%6,%7}, {%8,%9}, {%0,%1,%2,%3};"
        : "+f"(c[0]), "+f"(c[1]), "+f"(c[2]), "+f"(c[3])
        : "r"(a[0]), "r"(a[1]), "r"(a[2]), "r"(a[3]), "r"(b0), "r"(b1));
}

// ---------------- prep: zero accum + pack all weights to fp16 ----------------
__global__ void pack_all_kernel(const float* __restrict__ Wi, const float* __restrict__ Wh,
                                const float* __restrict__ Wz) {
    int idx = blockIdx.x * 256 + threadIdx.x;
    if (blockIdx.x == 0) {
        for (int t = threadIdx.x; t < NB * NC; t += 256) g_bagsum[t] = 0.0f;
        if (threadIdx.x < NB) g_bagcnt[threadIdx.x] = 0.0f;
    }
    if (idx < 256 * KP1) {
        int r = idx >> 10, k = idx & 1023;
        g_w1p[idx] = __float2half_rn(k < IN_DIM ? Wi[r * IN_DIM + k] : 0.0f);
    } else if (idx < 256 * KP1 + 256 * HD) {
        int j = idx - 256 * KP1;
        g_w2p[j] = __float2half_rn(Wh[j]);
    } else if (idx < 256 * KP1 + 256 * HD + ZD * HD) {
        int j = idx - 256 * KP1 - 256 * HD;
        g_wzp[j] = __float2half_rn(Wz[j]);
    }
}

// =================== GEMM1: 256 threads, 128x256 tile, 64x64 warp tiles, occ 1 ===================
#define G1_ASTG 10240                        /* 128 rows * 80B */
#define G1_BSTG 20480                        /* 256 rows * 80B */
#define G1_OFF_A 0                           /* 2 stages */
#define G1_OFF_B (2 * G1_ASTG)               /* 4 stages */
#define G1_OFF_BIAS (G1_OFF_B + 4 * G1_BSTG) /* 102400 */
#define G1_SMEM (G1_OFF_BIAS + 1024)         /* 103424 */

__global__ __launch_bounds__(256, 1)
void gemm1_kernel(const float* __restrict__ X, const __half* __restrict__ Bp,
                  const float* __restrict__ bias, __half* __restrict__ h1out, int N)
{
    extern __shared__ char smem[];
    const uint32_t su = s2u(smem);
    const int tid = threadIdx.x, lane = tid & 31, wid = tid >> 5;
    const int warp_m = wid & 1, warp_n = wid >> 1;   // 2 x 4 warps, warp tile 64x64

    float* s_bias = (float*)(smem + G1_OFF_BIAS);
    s_bias[tid] = bias[tid];

    const size_t rowbase = (size_t)blockIdx.x * 128;
    const int arow  = tid >> 1;              // 0..127
    const int ahalf = tid & 1;               // 16-float half of 32-k chunk
    const bool rowok = (rowbase + arow) < (size_t)N;
    const float* xrow = X + (rowbase + arow) * IN_DIM;

    float4 ar[4];
    auto ldgA = [&](int c) {
        int k0 = c * 32 + ahalf * 16;
#pragma unroll
        for (int q = 0; q < 4; q++) {
            int k = k0 + q * 4;
            ar[q] = (rowok && k < IN_DIM) ? *reinterpret_cast<const float4*>(xrow + k)
                                          : make_float4(0.f, 0.f, 0.f, 0.f);
        }
    };
    auto stsA = [&](int st) {
        __half2 h[8];
#pragma unroll
        for (int q = 0; q < 4; q++) {
            h[q * 2 + 0] = __floats2half2_rn(ar[q].x, ar[q].y);
            h[q * 2 + 1] = __floats2half2_rn(ar[q].z, ar[q].w);
        }
        uint4* dst = reinterpret_cast<uint4*>(smem + G1_OFF_A + st * G1_ASTG
                                              + arow * 80 + ahalf * 32);
        const uint4* s = reinterpret_cast<const uint4*>(h);
        dst[0] = s[0]; dst[1] = s[1];
    };
    auto cpB = [&](int c, int st) {
        const uint32_t bb = su + G1_OFF_B + st * G1_BSTG;
#pragma unroll
        for (int i = 0; i < 4; i++) {
            int s = tid + i * 256;
            int row = s >> 2, seg = s & 3;
            cpa16(bb + row * 80 + seg * 16, Bp + (size_t)row * KP1 + c * 32 + seg * 8);
        }
        asm volatile("cp.async.commit_group;" ::: "memory");
    };

    float acc[4][8][4];
#pragma unroll
    for (int mt = 0; mt < 4; mt++)
#pragma unroll
        for (int nt = 0; nt < 8; nt++)
#pragma unroll
            for (int i = 0; i < 4; i++) acc[mt][nt][i] = 0.0f;

    ldgA(0); stsA(0);
    ldgA(1);
    cpB(0, 0); cpB(1, 1); cpB(2, 2);

    const int a_r = lane & 15, a_k = (lane >> 4) * 8;
    const int b_n = (lane & 7) + ((lane >> 4) << 3);
    const int b_k = ((lane >> 3) & 1) * 8;

    constexpr int NCH = KP1 / 32;            // 32
    for (int c = 0; c < NCH; c++) {
        if (c < NCH - 2)       asm volatile("cp.async.wait_group 2;" ::: "memory");
        else if (c == NCH - 2) asm volatile("cp.async.wait_group 1;" ::: "memory");
        else                   asm volatile("cp.async.wait_group 0;" ::: "memory");
        __syncthreads();
        if (c + 3 < NCH) cpB(c + 3, (c + 3) & 3);
        if (c + 1 < NCH) stsA((c + 1) & 1);
        if (c + 2 < NCH) ldgA(c + 2);

        const uint32_t ab = su + G1_OFF_A + (c & 1) * G1_ASTG;
        const uint32_t bb = su + G1_OFF_B + (c & 3) * G1_BSTG;
#pragma unroll
        for (int s = 0; s < 2; s++) {
            uint32_t a[4][4];
#pragma unroll
            for (int mt = 0; mt < 4; mt++)
                ldx4(a[mt][0], a[mt][1], a[mt][2], a[mt][3],
                     ab + (warp_m * 64 + mt * 16 + a_r) * 80 + (s * 16 + a_k) * 2);
            uint32_t b[4][4];
#pragma unroll
            for (int p = 0; p < 4; p++)
                ldx4(b[p][0], b[p][1], b[p][2], b[p][3],
                     bb + (warp_n * 64 + p * 16 + b_n) * 80 + (s * 16 + b_k) * 2);
#pragma unroll
            for (int mt = 0; mt < 4; mt++)
#pragma unroll
                for (int nt = 0; nt < 8; nt++)
                    mma16816(acc[mt][nt], a[mt], b[nt >> 1][(nt & 1) * 2],
                             b[nt >> 1][(nt & 1) * 2 + 1]);
        }
    }

    // epilogue
#pragma unroll
    for (int mt = 0; mt < 4; mt++) {
#pragma unroll
        for (int nt = 0; nt < 8; nt++) {
            int col = warp_n * 64 + nt * 8 + (lane & 3) * 2;
            int r0 = warp_m * 64 + mt * 16 + (lane >> 2);
            float v0 = lrelu(acc[mt][nt][0] + s_bias[col]);
            float v1 = lrelu(acc[mt][nt][1] + s_bias[col + 1]);
            float v2 = lrelu(acc[mt][nt][2] + s_bias[col]);
            float v3 = lrelu(acc[mt][nt][3] + s_bias[col + 1]);
            *reinterpret_cast<__half2*>(h1out + (rowbase + r0) * HD + col) =
                __floats2half2_rn(v0, v1);
            *reinterpret_cast<__half2*>(h1out + (rowbase + r0 + 8) * HD + col) =
                __floats2half2_rn(v2, v3);
        }
    }
}

// =================== GEMM2: 256 threads, 64x256 tile, occupancy 2, fused z (round-13) ===================
#define G2_ASTG 5120
#define G2_BSTG 20480
#define G2_OFF_A 0
#define G2_OFF_B (3 * G2_ASTG)
#define G2_OFF_H2 G2_OFF_B
#define G2_OFF_WZ (G2_OFF_B + 3 * G2_BSTG)
#define G2_OFF_BIAS (G2_OFF_WZ + 16896)
#define G2_OFF_BZ (G2_OFF_BIAS + 1024)
#define G2_SMEM (G2_OFF_BZ + 128)

__global__ __launch_bounds__(256, 2)
void gemm2_kernel(const __half* __restrict__ A, const __half* __restrict__ Bp,
                  const float* __restrict__ bias,
                  const __half* __restrict__ Wzp, const float* __restrict__ bz,
                  float* __restrict__ zout)
{
    extern __shared__ char smem[];
    const uint32_t su = s2u(smem);
    const int tid = threadIdx.x, lane = tid & 31, wid = tid >> 5;
    const int warp_m = wid & 1, warp_n = wid >> 1;

    float* s_bias = (float*)(smem + G2_OFF_BIAS);
    if (tid < 256) s_bias[tid] = bias[tid];
    {
        float* s_bz = (float*)(smem + G2_OFF_BZ);
        if (tid < ZD) s_bz[tid] = bz[tid];
        for (int c = tid; c < 32 * 32; c += 256) {
            int row = c >> 5, seg = c & 31;
            uint4 v = *reinterpret_cast<const uint4*>(Wzp + (size_t)row * HD + seg * 8);
            *reinterpret_cast<uint4*>(smem + G2_OFF_WZ + row * 528 + seg * 16) = v;
        }
    }

    const size_t rowbase = (size_t)blockIdx.x * 64;
    constexpr int NCH = HD / 32;

    const int a_r = lane & 15, a_k = (lane >> 4) * 8;
    const int b_n = (lane & 7) + ((lane >> 4) << 3);
    const int b_k = ((lane >> 3) & 1) * 8;

    float acc[2][8][4];
#pragma unroll
    for (int mt = 0; mt < 2; mt++)
#pragma unroll
        for (int nt = 0; nt < 8; nt++)
#pragma unroll
            for (int i = 0; i < 4; i++) acc[mt][nt][i] = 0.0f;

    auto load_chunk = [&](int c, int st) {
        const int k0 = c * 32;
        const uint32_t ab = su + G2_OFF_A + st * G2_ASTG;
        const uint32_t bb = su + G2_OFF_B + st * G2_BSTG;
        {
            int row = tid >> 2, kseg = tid & 3;
            cpa16(ab + row * 80 + kseg * 16, A + (rowbase + row) * HD + k0 + kseg * 8);
        }
#pragma unroll
        for (int i = 0; i < 4; i++) {
            int s = tid + i * 256;
            int row = s >> 2, kseg = s & 3;
            cpa16(bb + row * 80 + kseg * 16, Bp + (size_t)row * HD + k0 + kseg * 8);
        }
        asm volatile("cp.async.commit_group;" ::: "memory");
    };

    load_chunk(0, 0);
    load_chunk(1, 1);
    load_chunk(2, 2);

    for (int c = 0; c < NCH; c++) {
        if (c < NCH - 2)       asm volatile("cp.async.wait_group 2;" ::: "memory");
        else if (c == NCH - 2) asm volatile("cp.async.wait_group 1;" ::: "memory");
        else                   asm volatile("cp.async.wait_group 0;" ::: "memory");
        __syncthreads();

        const int st = c % 3;
        const uint32_t ab = su + G2_OFF_A + st * G2_ASTG;
        const uint32_t bb = su + G2_OFF_B + st * G2_BSTG;
#pragma unroll
        for (int s = 0; s < 2; s++) {
            uint32_t a[2][4];
#pragma unroll
            for (int mt = 0; mt < 2; mt++)
                ldx4(a[mt][0], a[mt][1], a[mt][2], a[mt][3],
                     ab + (warp_m * 32 + mt * 16 + a_r) * 80 + (s * 16 + a_k) * 2);
            uint32_t b[4][4];
#pragma unroll
            for (int p = 0; p < 4; p++)
                ldx4(b[p][0], b[p][1], b[p][2], b[p][3],
                     bb + (warp_n * 64 + p * 16 + b_n) * 80 + (s * 16 + b_k) * 2);
#pragma unroll
            for (int mt = 0; mt < 2; mt++)
#pragma unroll
                for (int nt = 0; nt < 8; nt++)
                    mma16816(acc[mt][nt], a[mt], b[nt >> 1][(nt & 1) * 2],
                             b[nt >> 1][(nt & 1) * 2 + 1]);
        }
        __syncthreads();
        if (c + 3 < NCH) load_chunk(c + 3, (c + 3) % 3);
    }
    __syncthreads();

#pragma unroll
    for (int mt = 0; mt < 2; mt++) {
#pragma unroll
        for (int nt = 0; nt < 8; nt++) {
            int col = warp_n * 64 + nt * 8 + (lane & 3) * 2;
            int r0 = warp_m * 32 + mt * 16 + (lane >> 2);
            float v0 = lrelu(acc[mt][nt][0] + s_bias[col]);
            float v1 = lrelu(acc[mt][nt][1] + s_bias[col + 1]);
            float v2 = lrelu(acc[mt][nt][2] + s_bias[col]);
            float v3 = lrelu(acc[mt][nt][3] + s_bias[col + 1]);
            *reinterpret_cast<__half2*>(smem + G2_OFF_H2 + r0 * 528 + col * 2) =
                __floats2half2_rn(v0, v1);
            *reinterpret_cast<__half2*>(smem + G2_OFF_H2 + (r0 + 8) * 528 + col * 2) =
                __floats2half2_rn(v2, v3);
        }
    }
    __syncthreads();

    if (wid < 4) {
        const float* s_bz = (const float*)(smem + G2_OFF_BZ);
        float zacc[4][4];
#pragma unroll
        for (int nt = 0; nt < 4; nt++)
#pragma unroll
            for (int i = 0; i < 4; i++) zacc[nt][i] = 0.0f;

        const uint32_t h2b = su + G2_OFF_H2;
        const uint32_t wzb = su + G2_OFF_WZ;
        const int arow = wid * 16 + a_r;
#pragma unroll 4
        for (int s = 0; s < 16; s++) {
            uint32_t a[4];
            ldx4(a[0], a[1], a[2], a[3], h2b + arow * 528 + (s * 16 + a_k) * 2);
            uint32_t b[2][4];
#pragma unroll
            for (int p = 0; p < 2; p++)
                ldx4(b[p][0], b[p][1], b[p][2], b[p][3],
                     wzb + (p * 16 + b_n) * 528 + (s * 16 + b_k) * 2);
#pragma unroll
            for (int nt = 0; nt < 4; nt++)
                mma16816(zacc[nt], a, b[nt >> 1][(nt & 1) * 2], b[nt >> 1][(nt & 1) * 2 + 1]);
        }
#pragma unroll
        for (int nt = 0; nt < 4; nt++) {
            int col = nt * 8 + (lane & 3) * 2;
            int r0 = wid * 16 + (lane >> 2);
            float2 v0, v1;
            v0.x = lrelu(zacc[nt][0] + s_bz[col]);
            v0.y = lrelu(zacc[nt][1] + s_bz[col + 1]);
            v1.x = lrelu(zacc[nt][2] + s_bz[col]);
            v1.y = lrelu(zacc[nt][3] + s_bz[col + 1]);
            *reinterpret_cast<float2*>(zout + (rowbase + r0) * ZD + col) = v0;
            *reinterpret_cast<float2*>(zout + (rowbase + r0 + 8) * ZD + col) = v1;
        }
    }
}

// ---------------- head: 2 cells/thread, warp-uniform segmented reduction ----------------
__global__ __launch_bounds__(256)
void head_kernel(const float* __restrict__ zin, const int* __restrict__ seg,
                 const float* __restrict__ protos, const float* __restrict__ Wclf, int N)
{
    __shared__ float sProto[NP * ZD];
    __shared__ float sPsq[NP];
    __shared__ float sWclf[NC * NP];
    __shared__ float sBag[NB * NC];
    __shared__ float sCnt[NB];

    const int tid = threadIdx.x;
    for (int i = tid; i < NP * ZD; i += 256) sProto[i] = protos[i];
    for (int i = tid; i < NC * NP; i += 256) sWclf[i] = Wclf[i];
    for (int i = tid; i < NB * NC; i += 256) sBag[i] = 0.0f;
    if (tid < NB) sCnt[tid] = 0.0f;
    __syncthreads();
    if (tid < NP) {
        float s = 0.0f;
#pragma unroll
        for (int j = 0; j < ZD; j++) { float p = sProto[tid * ZD + j]; s = fmaf(p, p, s); }
        sPsq[tid] = s;
    }
    __syncthreads();

    const int lane = tid & 31;
    const int cell0 = blockIdx.x * 512 + tid;
    const int cell1 = cell0 + 256;
    const bool v0ok = cell0 < N, v1ok = cell1 < N;

    float z0[ZD], z1[ZD];
    float zsq0 = 0.0f, zsq1 = 0.0f;
    if (v0ok) {
        const float4* zr = reinterpret_cast<const float4*>(zin + (size_t)cell0 * ZD);
#pragma unroll
        for (int j4 = 0; j4 < ZD / 4; j4++) {
            float4 v = zr[j4];
            z0[j4 * 4 + 0] = v.x; z0[j4 * 4 + 1] = v.y;
            z0[j4 * 4 + 2] = v.z; z0[j4 * 4 + 3] = v.w;
        }
#pragma unroll
        for (int j = 0; j < ZD; j++) zsq0 = fmaf(z0[j], z0[j], zsq0);
    } else {
#pragma unroll
        for (int j = 0; j < ZD; j++) z0[j] = 0.0f;
    }
    if (v1ok) {
        const float4* zr = reinterpret_cast<const float4*>(zin + (size_t)cell1 * ZD);
#pragma unroll
        for (int j4 = 0; j4 < ZD / 4; j4++) {
            float4 v = zr[j4];
            z1[j4 * 4 + 0] = v.x; z1[j4 * 4 + 1] = v.y;
            z1[j4 * 4 + 2] = v.z; z1[j4 * 4 + 3] = v.w;
        }
#pragma unroll
        for (int j = 0; j < ZD; j++) zsq1 = fmaf(z1[j], z1[j], zsq1);
    } else {
#pragma unroll
        for (int j = 0; j < ZD; j++) z1[j] = 0.0f;
    }

    float cl0[NC], cl1[NC];
#pragma unroll
    for (int c = 0; c < NC; c++) { cl0[c] = 0.0f; cl1[c] = 0.0f; }

#pragma unroll 2
    for (int p = 0; p < NP; p++) {
        const float4* pp = reinterpret_cast<const float4*>(&sProto[p * ZD]);
        float d0 = 0.0f, d1 = 0.0f;
#pragma unroll
        for (int j4 = 0; j4 < ZD / 4; j4++) {
            float4 pv = pp[j4];
            d0 = fmaf(z0[j4 * 4 + 0], pv.x, d0); d1 = fmaf(z1[j4 * 4 + 0], pv.x, d1);
            d0 = fmaf(z0[j4 * 4 + 1], pv.y, d0); d1 = fmaf(z1[j4 * 4 + 1], pv.y, d1);
            d0 = fmaf(z0[j4 * 4 + 2], pv.z, d0); d1 = fmaf(z1[j4 * 4 + 2], pv.z, d1);
            d0 = fmaf(z0[j4 * 4 + 3], pv.w, d0); d1 = fmaf(z1[j4 * 4 + 3], pv.w, d1);
        }
        float dd0 = zsq0 - 2.0f * d0 + sPsq[p] + 0.5f;
        float dd1 = zsq1 - 2.0f * d1 + sPsq[p] + 0.5f;
        float inv0 = __fdividef(1.0f, dd0);
        float inv1 = __fdividef(1.0f, dd1);
#pragma unroll
        for (int c = 0; c < NC; c++) {
            float w = sWclf[c * NP + p];
            cl0[c] = fmaf(inv0, w, cl0[c]);
            cl1[c] = fmaf(inv1, w, cl1[c]);
        }
    }

    int b0 = v0ok ? seg[cell0] : -1;
    int b1 = v1ok ? seg[cell1] : -1;

    {
        const int bb = __shfl_sync(0xFFFFFFFFu, b0, 0);
        const bool uni = __all_sync(0xFFFFFFFFu, b0 == bb && b0 >= 0);
        if (uni) {
#pragma unroll
            for (int off = 16; off > 0; off >>= 1)
#pragma unroll
                for (int c = 0; c < NC; c++)
                    cl0[c] += __shfl_xor_sync(0xFFFFFFFFu, cl0[c], off);
            if (lane < NC) atomicAdd(&sBag[bb * NC + lane], cl0[lane]);
            else if (lane == NC) atomicAdd(&sCnt[bb], 32.0f);
        } else if (v0ok) {
#pragma unroll
            for (int c = 0; c < NC; c++) atomicAdd(&sBag[b0 * NC + c], cl0[c]);
            atomicAdd(&sCnt[b0], 1.0f);
        }
    }
    {
        const int bb = __shfl_sync(0xFFFFFFFFu, b1, 0);
        const bool uni = __all_sync(0xFFFFFFFFu, b1 == bb && b1 >= 0);
        if (uni) {
#pragma unroll
            for (int off = 16; off > 0; off >>= 1)
#pragma unroll
                for (int c = 0; c < NC; c++)
                    cl1[c] += __shfl_xor_sync(0xFFFFFFFFu, cl1[c], off);
            if (lane < NC) atomicAdd(&sBag[bb * NC + lane], cl1[lane]);
            else if (lane == NC) atomicAdd(&sCnt[bb], 32.0f);
        } else if (v1ok) {
#pragma unroll
            for (int c = 0; c < NC; c++) atomicAdd(&sBag[b1 * NC + c], cl1[c]);
            atomicAdd(&sCnt[b1], 1.0f);
        }
    }
    __syncthreads();

    for (int i = tid; i < NB * NC; i += 256)
        if (sBag[i] != 0.0f) atomicAdd(&g_bagsum[i], sBag[i]);
    if (tid < NB && sCnt[tid] != 0.0f) atomicAdd(&g_bagcnt[tid], sCnt[tid]);
}

// ---------------- finalize ----------------
__global__ void finalize_kernel(const int* __restrict__ y, float* __restrict__ out,
                                int out_size)
{
    __shared__ float sLoss[NB];
    const int b = threadIdx.x;
    float l[NC];
    float cnt = fmaxf(g_bagcnt[b], 1.0f);
    float inv = 1.0f / cnt;
    float m = -1e30f;
#pragma unroll
    for (int c = 0; c < NC; c++) { l[c] = g_bagsum[b * NC + c] * inv; m = fmaxf(m, l[c]); }
    float se = 0.0f;
#pragma unroll
    for (int c = 0; c < NC; c++) se += expf(l[c] - m);
    float lse = logf(se);
    int yc = y[b];
    sLoss[b] = -(l[yc] - m - lse);

    float* lo;
    bool write_loss;
    if (out_size == NB * NC) { lo = out; write_loss = false; }
    else                     { lo = out + 1; write_loss = true; }
    if (out_size >= NB * NC) {
#pragma unroll
        for (int c = 0; c < NC; c++) lo[b * NC + c] = l[c];
    }
    __syncthreads();
    if (b == 0 && write_loss) {
        float s = 0.0f;
        for (int i = 0; i < NB; i++) s += sLoss[i];
        out[0] = s / (float)NB;
    }
}

// ---------------- launch ----------------
extern "C" void kernel_launch(void* const* d_in, const int* in_sizes, int n_in,
                              void* d_out, int out_size)
{
    const float* x      = (const float*)d_in[0];
    const int*   y      = (const int*)  d_in[1];
    const int*   seg    = (const int*)  d_in[2];
    const float* W_i    = (const float*)d_in[3];
    const float* b_i    = (const float*)d_in[4];
    const float* W_h    = (const float*)d_in[5];
    const float* b_h    = (const float*)d_in[6];
    const float* W_z    = (const float*)d_in[7];
    const float* b_z    = (const float*)d_in[8];
    const float* protos = (const float*)d_in[9];
    const float* W_clf  = (const float*)d_in[10];

    const int N = in_sizes[0] / IN_DIM;

    __half *h1, *w1p, *w2p, *wzp;
    float* z;
    cudaGetSymbolAddress((void**)&h1,  g_h1);
    cudaGetSymbolAddress((void**)&z,   g_z);
    cudaGetSymbolAddress((void**)&w1p, g_w1p);
    cudaGetSymbolAddress((void**)&w2p, g_w2p);
    cudaGetSymbolAddress((void**)&wzp, g_wzp);

    cudaFuncSetAttribute(gemm1_kernel, cudaFuncAttributeMaxDynamicSharedMemorySize, G1_SMEM);
    cudaFuncSetAttribute(gemm2_kernel, cudaFuncAttributeMaxDynamicSharedMemorySize, G2_SMEM);

    const int pack_total = 256 * KP1 + 256 * HD + ZD * HD;
    pack_all_kernel<<<(pack_total + 255) / 256, 256>>>(W_i, W_h, W_z);

    gemm1_kernel<<<MBLK, 256, G1_SMEM>>>(x, w1p, b_i, h1, N);
    gemm2_kernel<<<MBLK64, 256, G2_SMEM>>>(h1, w2p, b_h, wzp, b_z, z);

    head_kernel<<<NPAD / 512, 256>>>(z, seg, protos, W_clf, N);
    finalize_kernel<<<1, NB>>>(y, (float*)d_out, out_size);
}

// round 16
// speedup vs baseline: 1.5663x; 1.0661x over previous
#include <cuda_runtime.h>
#include <cuda_fp16.h>
#include <cstdint>
#include <math.h>

#define IN_DIM 1000
#define KP1 1024
#define HD 256
#define ZD 32
#define NP 64
#define NC 8
#define NB 64
#define MBLK64 3128
#define NPAD (MBLK64 * 64)

// ---------------- device scratch ----------------
__device__ __align__(16) __half g_h1 [(size_t)NPAD * HD];
__device__ __align__(16) float  g_z  [(size_t)NPAD * ZD];
__device__ __align__(16) __half g_w1p[256 * KP1];
__device__ __align__(16) __half g_w2p[256 * HD];
__device__ __align__(16) __half g_wzp[32 * HD];
__device__ float g_bagsum[NB * NC];
__device__ float g_bagcnt[NB];

__device__ __forceinline__ float lrelu(float v) { return v > 0.0f ? v : 0.01f * v; }

__device__ __forceinline__ uint32_t s2u(const void* p) {
    uint32_t a;
    asm("{ .reg .u64 t; cvta.to.shared.u64 t, %1; cvt.u32.u64 %0, t; }" : "=r"(a) : "l"(p));
    return a;
}
__device__ __forceinline__ void cpa16(uint32_t dst, const void* src) {
    asm volatile("cp.async.cg.shared.global [%0], [%1], 16;" :: "r"(dst), "l"(src) : "memory");
}
__device__ __forceinline__ void ldx4(uint32_t& r0, uint32_t& r1, uint32_t& r2, uint32_t& r3,
                                     uint32_t addr) {
    asm volatile("ldmatrix.sync.aligned.m8n8.x4.shared.b16 {%0,%1,%2,%3}, [%4];"
                 : "=r"(r0), "=r"(r1), "=r"(r2), "=r"(r3) : "r"(addr));
}
__device__ __forceinline__ void mma16816(float (&c)[4], const uint32_t (&a)[4],
                                         uint32_t b0, uint32_t b1) {
    asm volatile(
        "mma.sync.aligned.m16n8k16.row.col.f32.f16.f16.f32 "
        "{%0,%1,%2,%3}, {%4,%5,%6,%7}, {%8,%9}, {%0,%1,%2,%3};"
        : "+f"(c[0]), "+f"(c[1]), "+f"(c[2]), "+f"(c[3])
        : "r"(a[0]), "r"(a[1]), "r"(a[2]), "r"(a[3]), "r"(b0), "r"(b1));
}

// ---------------- prep: zero accum + pack all weights to fp16 ----------------
__global__ void pack_all_kernel(const float* __restrict__ Wi, const float* __restrict__ Wh,
                                const float* __restrict__ Wz) {
    int idx = blockIdx.x * 256 + threadIdx.x;
    if (blockIdx.x == 0) {
        for (int t = threadIdx.x; t < NB * NC; t += 256) g_bagsum[t] = 0.0f;
        if (threadIdx.x < NB) g_bagcnt[threadIdx.x] = 0.0f;
    }
    if (idx < 256 * KP1) {
        int r = idx >> 10, k = idx & 1023;
        g_w1p[idx] = __float2half_rn(k < IN_DIM ? Wi[r * IN_DIM + k] : 0.0f);
    } else if (idx < 256 * KP1 + 256 * HD) {
        int j = idx - 256 * KP1;
        g_w2p[j] = __float2half_rn(Wh[j]);
    } else if (idx < 256 * KP1 + 256 * HD + ZD * HD) {
        int j = idx - 256 * KP1 - 256 * HD;
        g_wzp[j] = __float2half_rn(Wz[j]);
    }
}

// =================== GEMM1: 256 threads, 64x256 tile, occupancy 2 ===================
#define G1_ASTG 5120
#define G1_BSTG 20480
#define G1_OFF_A 0
#define G1_OFF_B (2 * G1_ASTG)
#define G1_OFF_BIAS (G1_OFF_B + 4 * G1_BSTG)
#define G1_SMEM (G1_OFF_BIAS + 1024)

__global__ __launch_bounds__(256, 2)
void gemm1_kernel(const float* __restrict__ X, const __half* __restrict__ Bp,
                  const float* __restrict__ bias, __half* __restrict__ h1out, int N)
{
    extern __shared__ char smem[];
    const uint32_t su = s2u(smem);
    const int tid = threadIdx.x, lane = tid & 31, wid = tid >> 5;
    const int warp_m = wid & 1, warp_n = wid >> 1;

    float* s_bias = (float*)(smem + G1_OFF_BIAS);
    s_bias[tid] = bias[tid];

    const size_t rowbase = (size_t)blockIdx.x * 64;
    const int arow = tid >> 2;
    const int akq  = (tid & 3) * 8;
    const bool rowok = (rowbase + arow) < (size_t)N;
    const float* xrow = X + (rowbase + arow) * IN_DIM;

    float4 ar0, ar1;
    auto ldgA = [&](int c) {
        int k = c * 32 + akq;
        if (c < 31) {   // fast path: K fully in-bounds for chunks 0..30 (992 <= IN_DIM)
            if (rowok) {
                ar0 = *reinterpret_cast<const float4*>(xrow + k);
                ar1 = *reinterpret_cast<const float4*>(xrow + k + 4);
            } else {
                ar0 = make_float4(0.f, 0.f, 0.f, 0.f);
                ar1 = ar0;
            }
        } else {
            ar0 = (rowok && k     < IN_DIM) ? *reinterpret_cast<const float4*>(xrow + k)
                                            : make_float4(0.f, 0.f, 0.f, 0.f);
            ar1 = (rowok && k + 4 < IN_DIM) ? *reinterpret_cast<const float4*>(xrow + k + 4)
                                            : make_float4(0.f, 0.f, 0.f, 0.f);
        }
    };
    auto stsA = [&](int st) {
        __half2 h[4];
        h[0] = __floats2half2_rn(ar0.x, ar0.y); h[1] = __floats2half2_rn(ar0.z, ar0.w);
        h[2] = __floats2half2_rn(ar1.x, ar1.y); h[3] = __floats2half2_rn(ar1.z, ar1.w);
        *reinterpret_cast<uint4*>(smem + G1_OFF_A + st * G1_ASTG + arow * 80 + (tid & 3) * 16)
            = *reinterpret_cast<uint4*>(h);
    };
    auto cpB = [&](int c, int st) {
        const uint32_t bb = su + G1_OFF_B + st * G1_BSTG;
#pragma unroll
        for (int i = 0; i < 4; i++) {
            int s = tid + i * 256;
            int row = s >> 2, seg = s & 3;
            cpa16(bb + row * 80 + seg * 16, Bp + (size_t)row * KP1 + c * 32 + seg * 8);
        }
        asm volatile("cp.async.commit_group;" ::: "memory");
    };

    float acc[2][8][4];
#pragma unroll
    for (int mt = 0; mt < 2; mt++)
#pragma unroll
        for (int nt = 0; nt < 8; nt++)
#pragma unroll
            for (int i = 0; i < 4; i++) acc[mt][nt][i] = 0.0f;

    ldgA(0); stsA(0);
    ldgA(1);
    cpB(0, 0); cpB(1, 1); cpB(2, 2);

    const int a_r = lane & 15, a_k = (lane >> 4) * 8;
    const int b_n = (lane & 7) + ((lane >> 4) << 3);
    const int b_k = ((lane >> 3) & 1) * 8;

    constexpr int NCH = KP1 / 32;
    for (int c = 0; c < NCH; c++) {
        if (c < NCH - 2)       asm volatile("cp.async.wait_group 2;" ::: "memory");
        else if (c == NCH - 2) asm volatile("cp.async.wait_group 1;" ::: "memory");
        else                   asm volatile("cp.async.wait_group 0;" ::: "memory");
        __syncthreads();
        if (c + 3 < NCH) cpB(c + 3, (c + 3) & 3);
        if (c + 1 < NCH) stsA((c + 1) & 1);
        if (c + 2 < NCH) ldgA(c + 2);

        const uint32_t ab = su + G1_OFF_A + (c & 1) * G1_ASTG;
        const uint32_t bb = su + G1_OFF_B + (c & 3) * G1_BSTG;
#pragma unroll
        for (int s = 0; s < 2; s++) {
            uint32_t a[2][4];
#pragma unroll
            for (int mt = 0; mt < 2; mt++)
                ldx4(a[mt][0], a[mt][1], a[mt][2], a[mt][3],
                     ab + (warp_m * 32 + mt * 16 + a_r) * 80 + (s * 16 + a_k) * 2);
            uint32_t b[4][4];
#pragma unroll
            for (int p = 0; p < 4; p++)
                ldx4(b[p][0], b[p][1], b[p][2], b[p][3],
                     bb + (warp_n * 64 + p * 16 + b_n) * 80 + (s * 16 + b_k) * 2);
#pragma unroll
            for (int mt = 0; mt < 2; mt++)
#pragma unroll
                for (int nt = 0; nt < 8; nt++)
                    mma16816(acc[mt][nt], a[mt], b[nt >> 1][(nt & 1) * 2],
                             b[nt >> 1][(nt & 1) * 2 + 1]);
        }
    }

#pragma unroll
    for (int mt = 0; mt < 2; mt++) {
#pragma unroll
        for (int nt = 0; nt < 8; nt++) {
            int col = warp_n * 64 + nt * 8 + (lane & 3) * 2;
            int r0 = warp_m * 32 + mt * 16 + (lane >> 2);
            float v0 = lrelu(acc[mt][nt][0] + s_bias[col]);
            float v1 = lrelu(acc[mt][nt][1] + s_bias[col + 1]);
            float v2 = lrelu(acc[mt][nt][2] + s_bias[col]);
            float v3 = lrelu(acc[mt][nt][3] + s_bias[col + 1]);
            *reinterpret_cast<__half2*>(h1out + (rowbase + r0) * HD + col) =
                __floats2half2_rn(v0, v1);
            *reinterpret_cast<__half2*>(h1out + (rowbase + r0 + 8) * HD + col) =
                __floats2half2_rn(v2, v3);
        }
    }
}

// =================== GEMM2: 256 threads, 64x256 tile, occupancy 2, fused z ===================
#define G2_ASTG 5120
#define G2_BSTG 20480
#define G2_OFF_A 0
#define G2_OFF_B (3 * G2_ASTG)
#define G2_OFF_H2 G2_OFF_B
#define G2_OFF_WZ (G2_OFF_B + 3 * G2_BSTG)
#define G2_OFF_BIAS (G2_OFF_WZ + 16896)
#define G2_OFF_BZ (G2_OFF_BIAS + 1024)
#define G2_SMEM (G2_OFF_BZ + 128)

__global__ __launch_bounds__(256, 2)
void gemm2_kernel(const __half* __restrict__ A, const __half* __restrict__ Bp,
                  const float* __restrict__ bias,
                  const __half* __restrict__ Wzp, const float* __restrict__ bz,
                  float* __restrict__ zout)
{
    extern __shared__ char smem[];
    const uint32_t su = s2u(smem);
    const int tid = threadIdx.x, lane = tid & 31, wid = tid >> 5;
    const int warp_m = wid & 1, warp_n = wid >> 1;

    float* s_bias = (float*)(smem + G2_OFF_BIAS);
    if (tid < 256) s_bias[tid] = bias[tid];
    {
        float* s_bz = (float*)(smem + G2_OFF_BZ);
        if (tid < ZD) s_bz[tid] = bz[tid];
        for (int c = tid; c < 32 * 32; c += 256) {
            int row = c >> 5, seg = c & 31;
            uint4 v = *reinterpret_cast<const uint4*>(Wzp + (size_t)row * HD + seg * 8);
            *reinterpret_cast<uint4*>(smem + G2_OFF_WZ + row * 528 + seg * 16) = v;
        }
    }

    const size_t rowbase = (size_t)blockIdx.x * 64;
    constexpr int NCH = HD / 32;

    const int a_r = lane & 15, a_k = (lane >> 4) * 8;
    const int b_n = (lane & 7) + ((lane >> 4) << 3);
    const int b_k = ((lane >> 3) & 1) * 8;

    float acc[2][8][4];
#pragma unroll
    for (int mt = 0; mt < 2; mt++)
#pragma unroll
        for (int nt = 0; nt < 8; nt++)
#pragma unroll
            for (int i = 0; i < 4; i++) acc[mt][nt][i] = 0.0f;

    auto load_chunk = [&](int c, int st) {
        const int k0 = c * 32;
        const uint32_t ab = su + G2_OFF_A + st * G2_ASTG;
        const uint32_t bb = su + G2_OFF_B + st * G2_BSTG;
        {
            int row = tid >> 2, kseg = tid & 3;
            cpa16(ab + row * 80 + kseg * 16, A + (rowbase + row) * HD + k0 + kseg * 8);
        }
#pragma unroll
        for (int i = 0; i < 4; i++) {
            int s = tid + i * 256;
            int row = s >> 2, kseg = s & 3;
            cpa16(bb + row * 80 + kseg * 16, Bp + (size_t)row * HD + k0 + kseg * 8);
        }
        asm volatile("cp.async.commit_group;" ::: "memory");
    };

    load_chunk(0, 0);
    load_chunk(1, 1);
    load_chunk(2, 2);

    for (int c = 0; c < NCH; c++) {
        if (c < NCH - 2)       asm volatile("cp.async.wait_group 2;" ::: "memory");
        else if (c == NCH - 2) asm volatile("cp.async.wait_group 1;" ::: "memory");
        else                   asm volatile("cp.async.wait_group 0;" ::: "memory");
        __syncthreads();

        const int st = c % 3;
        const uint32_t ab = su + G2_OFF_A + st * G2_ASTG;
        const uint32_t bb = su + G2_OFF_B + st * G2_BSTG;
#pragma unroll
        for (int s = 0; s < 2; s++) {
            uint32_t a[2][4];
#pragma unroll
            for (int mt = 0; mt < 2; mt++)
                ldx4(a[mt][0], a[mt][1], a[mt][2], a[mt][3],
                     ab + (warp_m * 32 + mt * 16 + a_r) * 80 + (s * 16 + a_k) * 2);
            uint32_t b[4][4];
#pragma unroll
            for (int p = 0; p < 4; p++)
                ldx4(b[p][0], b[p][1], b[p][2], b[p][3],
                     bb + (warp_n * 64 + p * 16 + b_n) * 80 + (s * 16 + b_k) * 2);
#pragma unroll
            for (int mt = 0; mt < 2; mt++)
#pragma unroll
                for (int nt = 0; nt < 8; nt++)
                    mma16816(acc[mt][nt], a[mt], b[nt >> 1][(nt & 1) * 2],
                             b[nt >> 1][(nt & 1) * 2 + 1]);
        }
        __syncthreads();
        if (c + 3 < NCH) load_chunk(c + 3, (c + 3) % 3);
    }
    // (no extra barrier: the final loop iteration's trailing __syncthreads covers B-stage reuse)

#pragma unroll
    for (int mt = 0; mt < 2; mt++) {
#pragma unroll
        for (int nt = 0; nt < 8; nt++) {
            int col = warp_n * 64 + nt * 8 + (lane & 3) * 2;
            int r0 = warp_m * 32 + mt * 16 + (lane >> 2);
            float v0 = lrelu(acc[mt][nt][0] + s_bias[col]);
            float v1 = lrelu(acc[mt][nt][1] + s_bias[col + 1]);
            float v2 = lrelu(acc[mt][nt][2] + s_bias[col]);
            float v3 = lrelu(acc[mt][nt][3] + s_bias[col + 1]);
            *reinterpret_cast<__half2*>(smem + G2_OFF_H2 + r0 * 528 + col * 2) =
                __floats2half2_rn(v0, v1);
            *reinterpret_cast<__half2*>(smem + G2_OFF_H2 + (r0 + 8) * 528 + col * 2) =
                __floats2half2_rn(v2, v3);
        }
    }
    __syncthreads();

    if (wid < 4) {
        const float* s_bz = (const float*)(smem + G2_OFF_BZ);
        float zacc[4][4];
#pragma unroll
        for (int nt = 0; nt < 4; nt++)
#pragma unroll
            for (int i = 0; i < 4; i++) zacc[nt][i] = 0.0f;

        const uint32_t h2b = su + G2_OFF_H2;
        const uint32_t wzb = su + G2_OFF_WZ;
        const int arow = wid * 16 + a_r;
#pragma unroll 4
        for (int s = 0; s < 16; s++) {
            uint32_t a[4];
            ldx4(a[0], a[1], a[2], a[3], h2b + arow * 528 + (s * 16 + a_k) * 2);
            uint32_t b[2][4];
#pragma unroll
            for (int p = 0; p < 2; p++)
                ldx4(b[p][0], b[p][1], b[p][2], b[p][3],
                     wzb + (p * 16 + b_n) * 528 + (s * 16 + b_k) * 2);
#pragma unroll
            for (int nt = 0; nt < 4; nt++)
                mma16816(zacc[nt], a, b[nt >> 1][(nt & 1) * 2], b[nt >> 1][(nt & 1) * 2 + 1]);
        }
#pragma unroll
        for (int nt = 0; nt < 4; nt++) {
            int col = nt * 8 + (lane & 3) * 2;
            int r0 = wid * 16 + (lane >> 2);
            float2 v0, v1;
            v0.x = lrelu(zacc[nt][0] + s_bz[col]);
            v0.y = lrelu(zacc[nt][1] + s_bz[col + 1]);
            v1.x = lrelu(zacc[nt][2] + s_bz[col]);
            v1.y = lrelu(zacc[nt][3] + s_bz[col + 1]);
            *reinterpret_cast<float2*>(zout + (rowbase + r0) * ZD + col) = v0;
            *reinterpret_cast<float2*>(zout + (rowbase + r0 + 8) * ZD + col) = v1;
        }
    }
}

// ---------------- head: 2 cells/thread, warp-uniform segmented reduction ----------------
__global__ __launch_bounds__(256)
void head_kernel(const float* __restrict__ zin, const int* __restrict__ seg,
                 const float* __restrict__ protos, const float* __restrict__ Wclf, int N)
{
    __shared__ float sProto[NP * ZD];
    __shared__ float sPsq[NP];
    __shared__ float sWclf[NC * NP];
    __shared__ float sBag[NB * NC];
    __shared__ float sCnt[NB];

    const int tid = threadIdx.x;
    for (int i = tid; i < NP * ZD; i += 256) sProto[i] = protos[i];
    for (int i = tid; i < NC * NP; i += 256) sWclf[i] = Wclf[i];
    for (int i = tid; i < NB * NC; i += 256) sBag[i] = 0.0f;
    if (tid < NB) sCnt[tid] = 0.0f;
    __syncthreads();
    if (tid < NP) {
        float s = 0.0f;
#pragma unroll
        for (int j = 0; j < ZD; j++) { float p = sProto[tid * ZD + j]; s = fmaf(p, p, s); }
        sPsq[tid] = s;
    }
    __syncthreads();

    const int lane = tid & 31;
    const int cell0 = blockIdx.x * 512 + tid;
    const int cell1 = cell0 + 256;
    const bool v0ok = cell0 < N, v1ok = cell1 < N;

    // hoist segment ids so their load latency overlaps the proto FMA chain
    int b0 = v0ok ? seg[cell0] : -1;
    int b1 = v1ok ? seg[cell1] : -1;

    float z0[ZD], z1[ZD];
    float zsq0 = 0.0f, zsq1 = 0.0f;
    if (v0ok) {
        const float4* zr = reinterpret_cast<const float4*>(zin + (size_t)cell0 * ZD);
#pragma unroll
        for (int j4 = 0; j4 < ZD / 4; j4++) {
            float4 v = zr[j4];
            z0[j4 * 4 + 0] = v.x; z0[j4 * 4 + 1] = v.y;
            z0[j4 * 4 + 2] = v.z; z0[j4 * 4 + 3] = v.w;
        }
#pragma unroll
        for (int j = 0; j < ZD; j++) zsq0 = fmaf(z0[j], z0[j], zsq0);
    } else {
#pragma unroll
        for (int j = 0; j < ZD; j++) z0[j] = 0.0f;
    }
    if (v1ok) {
        const float4* zr = reinterpret_cast<const float4*>(zin + (size_t)cell1 * ZD);
#pragma unroll
        for (int j4 = 0; j4 < ZD / 4; j4++) {
            float4 v = zr[j4];
            z1[j4 * 4 + 0] = v.x; z1[j4 * 4 + 1] = v.y;
            z1[j4 * 4 + 2] = v.z; z1[j4 * 4 + 3] = v.w;
        }
#pragma unroll
        for (int j = 0; j < ZD; j++) zsq1 = fmaf(z1[j], z1[j], zsq1);
    } else {
#pragma unroll
        for (int j = 0; j < ZD; j++) z1[j] = 0.0f;
    }

    float cl0[NC], cl1[NC];
#pragma unroll
    for (int c = 0; c < NC; c++) { cl0[c] = 0.0f; cl1[c] = 0.0f; }

#pragma unroll 2
    for (int p = 0; p < NP; p++) {
        const float4* pp = reinterpret_cast<const float4*>(&sProto[p * ZD]);
        float d0 = 0.0f, d1 = 0.0f;
#pragma unroll
        for (int j4 = 0; j4 < ZD / 4; j4++) {
            float4 pv = pp[j4];
            d0 = fmaf(z0[j4 * 4 + 0], pv.x, d0); d1 = fmaf(z1[j4 * 4 + 0], pv.x, d1);
            d0 = fmaf(z0[j4 * 4 + 1], pv.y, d0); d1 = fmaf(z1[j4 * 4 + 1], pv.y, d1);
            d0 = fmaf(z0[j4 * 4 + 2], pv.z, d0); d1 = fmaf(z1[j4 * 4 + 2], pv.z, d1);
            d0 = fmaf(z0[j4 * 4 + 3], pv.w, d0); d1 = fmaf(z1[j4 * 4 + 3], pv.w, d1);
        }
        float dd0 = zsq0 - 2.0f * d0 + sPsq[p] + 0.5f;
        float dd1 = zsq1 - 2.0f * d1 + sPsq[p] + 0.5f;
        float inv0 = __fdividef(1.0f, dd0);
        float inv1 = __fdividef(1.0f, dd1);
#pragma unroll
        for (int c = 0; c < NC; c++) {
            float w = sWclf[c * NP + p];
            cl0[c] = fmaf(inv0, w, cl0[c]);
            cl1[c] = fmaf(inv1, w, cl1[c]);
        }
    }

    {
        const int bb = __shfl_sync(0xFFFFFFFFu, b0, 0);
        const bool uni = __all_sync(0xFFFFFFFFu, b0 == bb && b0 >= 0);
        if (uni) {
#pragma unroll
            for (int off = 16; off > 0; off >>= 1)
#pragma unroll
                for (int c = 0; c < NC; c++)
                    cl0[c] += __shfl_xor_sync(0xFFFFFFFFu, cl0[c], off);
            if (lane < NC) atomicAdd(&sBag[bb * NC + lane], cl0[lane]);
            else if (lane == NC) atomicAdd(&sCnt[bb], 32.0f);
        } else if (v0ok) {
#pragma unroll
            for (int c = 0; c < NC; c++) atomicAdd(&sBag[b0 * NC + c], cl0[c]);
            atomicAdd(&sCnt[b0], 1.0f);
        }
    }
    {
        const int bb = __shfl_sync(0xFFFFFFFFu, b1, 0);
        const bool uni = __all_sync(0xFFFFFFFFu, b1 == bb && b1 >= 0);
        if (uni) {
#pragma unroll
            for (int off = 16; off > 0; off >>= 1)
#pragma unroll
                for (int c = 0; c < NC; c++)
                    cl1[c] += __shfl_xor_sync(0xFFFFFFFFu, cl1[c], off);
            if (lane < NC) atomicAdd(&sBag[bb * NC + lane], cl1[lane]);
            else if (lane == NC) atomicAdd(&sCnt[bb], 32.0f);
        } else if (v1ok) {
#pragma unroll
            for (int c = 0; c < NC; c++) atomicAdd(&sBag[b1 * NC + c], cl1[c]);
            atomicAdd(&sCnt[b1], 1.0f);
        }
    }
    __syncthreads();

    for (int i = tid; i < NB * NC; i += 256)
        if (sBag[i] != 0.0f) atomicAdd(&g_bagsum[i], sBag[i]);
    if (tid < NB && sCnt[tid] != 0.0f) atomicAdd(&g_bagcnt[tid], sCnt[tid]);
}

// ---------------- finalize ----------------
__global__ void finalize_kernel(const int* __restrict__ y, float* __restrict__ out,
                                int out_size)
{
    __shared__ float sLoss[NB];
    const int b = threadIdx.x;
    float l[NC];
    float cnt = fmaxf(g_bagcnt[b], 1.0f);
    float inv = 1.0f / cnt;
    float m = -1e30f;
#pragma unroll
    for (int c = 0; c < NC; c++) { l[c] = g_bagsum[b * NC + c] * inv; m = fmaxf(m, l[c]); }
    float se = 0.0f;
#pragma unroll
    for (int c = 0; c < NC; c++) se += expf(l[c] - m);
    float lse = logf(se);
    int yc = y[b];
    sLoss[b] = -(l[yc] - m - lse);

    float* lo;
    bool write_loss;
    if (out_size == NB * NC) { lo = out; write_loss = false; }
    else                     { lo = out + 1; write_loss = true; }
    if (out_size >= NB * NC) {
#pragma unroll
        for (int c = 0; c < NC; c++) lo[b * NC + c] = l[c];
    }
    __syncthreads();
    if (b == 0 && write_loss) {
        float s = 0.0f;
        for (int i = 0; i < NB; i++) s += sLoss[i];
        out[0] = s / (float)NB;
    }
}

// ---------------- launch ----------------
extern "C" void kernel_launch(void* const* d_in, const int* in_sizes, int n_in,
                              void* d_out, int out_size)
{
    const float* x      = (const float*)d_in[0];
    const int*   y      = (const int*)  d_in[1];
    const int*   seg    = (const int*)  d_in[2];
    const float* W_i    = (const float*)d_in[3];
    const float* b_i    = (const float*)d_in[4];
    const float* W_h    = (const float*)d_in[5];
    const float* b_h    = (const float*)d_in[6];
    const float* W_z    = (const float*)d_in[7];
    const float* b_z    = (const float*)d_in[8];
    const float* protos = (const float*)d_in[9];
    const float* W_clf  = (const float*)d_in[10];

    const int N = in_sizes[0] / IN_DIM;

    __half *h1, *w1p, *w2p, *wzp;
    float* z;
    cudaGetSymbolAddress((void**)&h1,  g_h1);
    cudaGetSymbolAddress((void**)&z,   g_z);
    cudaGetSymbolAddress((void**)&w1p, g_w1p);
    cudaGetSymbolAddress((void**)&w2p, g_w2p);
    cudaGetSymbolAddress((void**)&wzp, g_wzp);

    cudaFuncSetAttribute(gemm1_kernel, cudaFuncAttributeMaxDynamicSharedMemorySize, G1_SMEM);
    cudaFuncSetAttribute(gemm2_kernel, cudaFuncAttributeMaxDynamicSharedMemorySize, G2_SMEM);

    const int pack_total = 256 * KP1 + 256 * HD + ZD * HD;
    pack_all_kernel<<<(pack_total + 255) / 256, 256>>>(W_i, W_h, W_z);

    gemm1_kernel<<<MBLK64, 256, G1_SMEM>>>(x, w1p, b_i, h1, N);
    gemm2_kernel<<<MBLK64, 256, G2_SMEM>>>(h1, w2p, b_h, wzp, b_z, z);

    head_kernel<<<NPAD / 512, 256>>>(z, seg, protos, W_clf, N);
    finalize_kernel<<<1, NB>>>(y, (float*)d_out, out_size);
}